// round 12
// baseline (speedup 1.0000x reference)
#include <cuda_runtime.h>
#include <cuda_bf16.h>
#include <cstdint>
#include <math.h>

#define F_IN    4096
#define NBLK    2048
#define NROUNDS 12
#define NDR     6          // 6 fused double-rounds
#define M_ROWS  8192
#define N_ROWS  4096

#define ROT_R 2
#define ROT_T 512

// ---------------- scratch (static device arrays; no allocation) ----------------
__device__ float       g_scratch[(size_t)M_ROWS * F_IN];   // 128 MB, reused x then w
__device__ signed char g_qx[(size_t)M_ROWS * F_IN];        // 32 MB
__device__ signed char g_qw[(size_t)N_ROWS * F_IN];        // 16 MB
__device__ int         g_sx[M_ROWS];
__device__ int         g_sw[N_ROWS];
__device__ unsigned    g_mm[4];                            // minx,maxx,minw,maxw (ordered-uint)

// fused double-round tables (prep_kernel output; L2-resident, reused by all CTAs)
__device__ int4   g_fidx[NDR * NBLK];   // 4 source features per dest pair
__device__ float4 g_fw0[NDR * NBLK];    // coeff row for dest element 0
__device__ float4 g_fw1[NDR * NBLK];    // coeff row for dest element 1

__device__ __forceinline__ unsigned f2u_ord(float f) {
    unsigned u = __float_as_uint(f);
    return (u & 0x80000000u) ? ~u : (u | 0x80000000u);
}
__device__ __forceinline__ float u2f_ord(unsigned u) {
    return __uint_as_float((u & 0x80000000u) ? (u ^ 0x80000000u) : ~u);
}

__global__ void init_kernel() {
    g_mm[0] = 0xFFFFFFFFu; g_mm[1] = 0u;
    g_mm[2] = 0xFFFFFFFFu; g_mm[3] = 0u;
}

// ---------------- prep: fuse round pairs (2dr, 2dr+1) into gather4 + 2x4 coeffs ----------------
__global__ __launch_bounds__(256) void prep_kernel(
    const int* __restrict__ perm, const float* __restrict__ mats)
{
    const int idx = blockIdx.x * 256 + threadIdx.x;
    if (idx >= NDR * NBLK) return;
    const int dr = idx / NBLK;
    const int k  = idx % NBLK;
    const int r0 = 2 * dr, r1 = 2 * dr + 1;

    const int j0 = perm[r1 * F_IN + 2 * k];
    const int j1 = perm[r1 * F_IN + 2 * k + 1];
    const int m0 = j0 >> 1, b0 = j0 & 1;
    const int m1 = j1 >> 1, b1 = j1 & 1;

    int4 s;
    s.x = perm[r0 * F_IN + 2 * m0];
    s.y = perm[r0 * F_IN + 2 * m0 + 1];
    s.z = perm[r0 * F_IN + 2 * m1];
    s.w = perm[r0 * F_IN + 2 * m1 + 1];

    const float4* m4 = (const float4*)mats;            // row-major 2x2: {00,01,10,11}
    const float4 M1 = m4[(size_t)r1 * NBLK + k];
    const float4 Ma = m4[(size_t)r0 * NBLK + m0];
    const float4 Mb = m4[(size_t)r0 * NBLK + m1];
    const float a0 = b0 ? Ma.z : Ma.x, a1 = b0 ? Ma.w : Ma.y;   // row bit_b of M_{r0}[m_b]
    const float c0 = b1 ? Mb.z : Mb.x, c1 = b1 ? Mb.w : Mb.y;

    g_fidx[idx] = s;
    g_fw0[idx] = make_float4(M1.x * a0, M1.x * a1, M1.y * c0, M1.y * c1);
    g_fw1[idx] = make_float4(M1.z * a0, M1.z * a1, M1.w * c0, M1.w * c1);
}

// ---------------- rotation: 6 fused stages in smem, 2 rows/CTA (3 CTAs/SM) ----------------
__global__ __launch_bounds__(ROT_T) void rotate_kernel(
    const float* __restrict__ src, int sel)
{
    extern __shared__ float sm[];
    float* bufA = sm;                    // row-major tile / interleaved pong
    float* bufB = sm + ROT_R * F_IN;     // interleaved ping
    const int tid = threadIdx.x;
    const size_t base = (size_t)blockIdx.x * ROT_R * F_IN;

    // coalesced load of 2 rows (row-major into bufA)
    {
        const float4* g = (const float4*)(src + base);
        float4* b = (float4*)bufA;
        #pragma unroll
        for (int i = 0; i < (ROT_R * F_IN / 4) / ROT_T; i++)
            b[tid + i * ROT_T] = g[tid + i * ROT_T];
    }
    __syncthreads();

    // interleave: bufB2[f] = {row0[f], row1[f]}
    {
        float2* b2 = (float2*)bufB;
        #pragma unroll
        for (int i = 0; i < F_IN / ROT_T; i++) {
            const int f = tid + i * ROT_T;
            b2[f] = make_float2(bufA[f], bufA[F_IN + f]);
        }
    }
    __syncthreads();

    float* cur = bufB;
    float* nxt = bufA;
    float mn = 3.0e38f, mx = -3.0e38f;

    for (int dr = 0; dr < NDR; dr++) {
        const int4*   fi  = g_fidx + dr * NBLK;
        const float4* w0p = g_fw0 + dr * NBLK;
        const float4* w1p = g_fw1 + dr * NBLK;
        const float2* cur2 = (const float2*)cur;
        float2* nxt2 = (float2*)nxt;
        const bool last = (dr == NDR - 1);
        #pragma unroll
        for (int b = 0; b < NBLK / ROT_T; b++) {
            const int k = tid + b * ROT_T;
            const int4   s  = fi[k];
            const float4 w0 = w0p[k];
            const float4 w1 = w1p[k];
            const float2 va = cur2[s.x];
            const float2 vb = cur2[s.y];
            const float2 vc = cur2[s.z];
            const float2 vd = cur2[s.w];
            float2 o0, o1;
            o0.x = w0.x * va.x + w0.y * vb.x + w0.z * vc.x + w0.w * vd.x;
            o0.y = w0.x * va.y + w0.y * vb.y + w0.z * vc.y + w0.w * vd.y;
            o1.x = w1.x * va.x + w1.y * vb.x + w1.z * vc.x + w1.w * vd.x;
            o1.y = w1.x * va.y + w1.y * vb.y + w1.z * vc.y + w1.w * vd.y;
            nxt2[2 * k]     = o0;
            nxt2[2 * k + 1] = o1;
            if (last) {
                mn = fminf(mn, fminf(fminf(o0.x, o0.y), fminf(o1.x, o1.y)));
                mx = fmaxf(mx, fmaxf(fmaxf(o0.x, o0.y), fmaxf(o1.x, o1.y)));
            }
        }
        __syncthreads();
        float* t = cur; cur = nxt; nxt = t;
    }

    // un-interleave, write row-major scratch (coalesced per row)
    {
        const float2* cur2 = (const float2*)cur;
        float* dst = g_scratch + base;
        #pragma unroll
        for (int i = 0; i < F_IN / ROT_T; i++) {
            const int f = tid + i * ROT_T;
            const float2 v = cur2[f];
            dst[f]        = v.x;
            dst[F_IN + f] = v.y;
        }
    }

    // block-reduce min/max -> one atomic pair per CTA
    #pragma unroll
    for (int o = 16; o > 0; o >>= 1) {
        mn = fminf(mn, __shfl_xor_sync(0xFFFFFFFFu, mn, o));
        mx = fmaxf(mx, __shfl_xor_sync(0xFFFFFFFFu, mx, o));
    }
    __shared__ float smn[ROT_T / 32], smx[ROT_T / 32];
    const int w = tid >> 5;
    if ((tid & 31) == 0) { smn[w] = mn; smx[w] = mx; }
    __syncthreads();
    if (tid == 0) {
        #pragma unroll
        for (int i = 1; i < ROT_T / 32; i++) {
            mn = fminf(mn, smn[i]); mx = fmaxf(mx, smx[i]);
        }
        atomicMin(&g_mm[sel], f2u_ord(mn));
        atomicMax(&g_mm[sel + 1], f2u_ord(mx));
    }
}

// ---------------- quantize: q = clip(round((t-lo)/s) - 128), + per-row sums ----------------
__global__ __launch_bounds__(256) void quant_kernel(int sel)
{
    const int row = blockIdx.x;
    const int tid = threadIdx.x;
    signed char* q = sel ? g_qw : g_qx;
    int* rowsum    = sel ? g_sw : g_sx;
    const float lo = u2f_ord(g_mm[sel ? 2 : 0]);
    const float hi = u2f_ord(g_mm[sel ? 3 : 1]);
    const float scale = (hi - lo) / 255.0f;

    const float4* s4 = (const float4*)(g_scratch + (size_t)row * F_IN);
    char4* q4 = (char4*)(q + (size_t)row * F_IN);
    int ssum = 0;
    #pragma unroll
    for (int i = 0; i < (F_IN / 4) / 256; i++) {
        const float4 v = s4[tid + i * 256];
        const int q0 = (int)fminf(fmaxf(rintf((v.x - lo) / scale) - 128.0f, -128.0f), 127.0f);
        const int q1 = (int)fminf(fmaxf(rintf((v.y - lo) / scale) - 128.0f, -128.0f), 127.0f);
        const int q2 = (int)fminf(fmaxf(rintf((v.z - lo) / scale) - 128.0f, -128.0f), 127.0f);
        const int q3 = (int)fminf(fmaxf(rintf((v.w - lo) / scale) - 128.0f, -128.0f), 127.0f);
        ssum += q0 + q1 + q2 + q3;
        char4 c;
        c.x = (signed char)q0; c.y = (signed char)q1;
        c.z = (signed char)q2; c.w = (signed char)q3;
        q4[tid + i * 256] = c;
    }
    #pragma unroll
    for (int o = 16; o > 0; o >>= 1)
        ssum += __shfl_xor_sync(0xFFFFFFFFu, ssum, o);
    __shared__ int ss[8];
    if ((tid & 31) == 0) ss[tid >> 5] = ssum;
    __syncthreads();
    if (tid == 0) {
        #pragma unroll
        for (int i = 1; i < 8; i++) ssum += ss[i];
        rowsum[row] = ssum;
    }
}

// ---------------- hybrid int8 GEMM: IMMA (tensor pipe) + dp4a (ALU pipe) ----------------
// Per warp per BK=128 tile: K[0:96] via 3 mma.sync ks-steps, K[96:128] via dp4a.
// dp4a thread->output mapping matches the mma d-fragment layout exactly, so both
// paths accumulate into the same d[16][4] registers.
#define BM 128
#define BN 128
#define BK 128
#define GSTAGES 3
#define SSTR 144   // 128B data + 16B pad: rows land on distinct 16B bank groups

#define A_STAGE_BYTES (BM * SSTR)
#define B_STAGE_BYTES (BN * SSTR)
#define GEMM_SMEM (GSTAGES * (A_STAGE_BYTES + B_STAGE_BYTES))

__device__ __forceinline__ void cp16(void* s, const void* g) {
    unsigned sa = (unsigned)__cvta_generic_to_shared(s);
    asm volatile("cp.async.cg.shared.global [%0], [%1], 16;\n" :: "r"(sa), "l"(g));
}
__device__ __forceinline__ void cp_commit() { asm volatile("cp.async.commit_group;\n"); }
__device__ __forceinline__ void cp_wait1()  { asm volatile("cp.async.wait_group 1;\n"); }
__device__ __forceinline__ void cp_wait0()  { asm volatile("cp.async.wait_group 0;\n"); }

__device__ __forceinline__ void ldsm4(int* r, const void* p) {
    unsigned a = (unsigned)__cvta_generic_to_shared(p);
    asm volatile("ldmatrix.sync.aligned.m8n8.x4.shared.b16 {%0,%1,%2,%3}, [%4];\n"
                 : "=r"(r[0]), "=r"(r[1]), "=r"(r[2]), "=r"(r[3]) : "r"(a));
}
__device__ __forceinline__ void ldsm2(int* r, const void* p) {
    unsigned a = (unsigned)__cvta_generic_to_shared(p);
    asm volatile("ldmatrix.sync.aligned.m8n8.x2.shared.b16 {%0,%1}, [%2];\n"
                 : "=r"(r[0]), "=r"(r[1]) : "r"(a));
}

__device__ __forceinline__ void mma_s8(int* d, const int* a, const int* b) {
    asm volatile(
        "mma.sync.aligned.m16n8k32.row.col.s32.s8.s8.s32 "
        "{%0,%1,%2,%3}, {%4,%5,%6,%7}, {%8,%9}, {%0,%1,%2,%3};\n"
        : "+r"(d[0]), "+r"(d[1]), "+r"(d[2]), "+r"(d[3])
        : "r"(a[0]), "r"(a[1]), "r"(a[2]), "r"(a[3]), "r"(b[0]), "r"(b[1]));
}

__device__ __forceinline__ void dp4a_acc(int& d, int a, int b) {
    asm volatile("dp4a.s32.s32 %0, %1, %2, %0;\n" : "+r"(d) : "r"(a), "r"(b));
}

__global__ __launch_bounds__(256, 1) void gemm_kernel(
    const float* __restrict__ bias, float* __restrict__ out)
{
    extern __shared__ signed char gsm[];
    const signed char* __restrict__ A = g_qx;   // [M][K]
    const signed char* __restrict__ B = g_qw;   // [N][K]
    const int K = F_IN;
    const int tid = threadIdx.x;
    const int lane = tid & 31;
    const int warp = tid >> 5;
    const int wm = warp & 1;    // 2 warps along M (64 rows each)
    const int wn = warp >> 1;   // 4 warps along N (32 cols each)
    const size_t aBase = (size_t)blockIdx.y * BM * K;
    const size_t bBase = (size_t)blockIdx.x * BN * K;

    int d[16][4];
    #pragma unroll
    for (int i = 0; i < 16; i++) { d[i][0] = d[i][1] = d[i][2] = d[i][3] = 0; }

    auto load_stage = [&](int st, int k0) {
        signed char* sa = gsm + st * A_STAGE_BYTES;
        signed char* sb = gsm + GSTAGES * A_STAGE_BYTES + st * B_STAGE_BYTES;
        #pragma unroll
        for (int i = 0; i < 4; i++) {
            const int idx = tid + i * 256;          // 1024 x 16B per matrix
            const int row = idx >> 3;
            const int c = (idx & 7) << 4;
            cp16(sa + row * SSTR + c, A + aBase + (size_t)row * K + k0 + c);
            cp16(sb + row * SSTR + c, B + bBase + (size_t)row * K + k0 + c);
        }
        cp_commit();
    };

    load_stage(0, 0);
    load_stage(1, BK);

    const int a_row_off = ((lane >> 3) & 1) * 8 + (lane & 7);
    const int a_col_off = (lane >> 4) * 16;
    const int b_row_off = (lane & 7);
    const int b_col_off = ((lane >> 3) & 1) * 16;
    const int dp_a_row = lane >> 2;          // dp4a A row within 8-group (4-way bcast)
    const int dp_b_col = (lane & 3) << 1;    // dp4a B row pair base (8-way bcast)

    const int NK = K / BK;   // 32
    for (int kt = 0; kt < NK; kt++) {
        const int st = kt % GSTAGES;
        if (kt + 2 < NK) cp_wait1(); else cp_wait0();
        __syncthreads();

        const signed char* sa = gsm + st * A_STAGE_BYTES;
        const signed char* sb = gsm + GSTAGES * A_STAGE_BYTES + st * B_STAGE_BYTES;

        // --- tensor pipe: K[0:96] via 3 IMMA ks-steps ---
        #pragma unroll
        for (int ks = 0; ks < 3; ks++) {
            const int cb = ks * 32;
            int a[4][4], b[4][2];
            #pragma unroll
            for (int i = 0; i < 4; i++) {
                const int r0 = wm * 64 + i * 16 + a_row_off;
                ldsm4(a[i], sa + r0 * SSTR + cb + a_col_off);
            }
            #pragma unroll
            for (int j = 0; j < 4; j++) {
                const int n0 = wn * 32 + j * 8 + b_row_off;
                ldsm2(b[j], sb + n0 * SSTR + cb + b_col_off);
            }
            #pragma unroll
            for (int i = 0; i < 4; i++)
                #pragma unroll
                for (int j = 0; j < 4; j++)
                    mma_s8(d[i * 4 + j], a[i], b[j]);
        }

        // --- ALU pipe: K[96:128] via dp4a, fragment-matched layout ---
        #pragma unroll
        for (int ch = 0; ch < 2; ch++) {
            const int cb = 96 + ch * 16;
            int av[8][4], bv[8][4];
            #pragma unroll
            for (int i = 0; i < 4; i++)
                #pragma unroll
                for (int h = 0; h < 2; h++) {
                    const int r0 = wm * 64 + i * 16 + h * 8 + dp_a_row;
                    const int4 v = *(const int4*)(sa + r0 * SSTR + cb);
                    av[i * 2 + h][0] = v.x; av[i * 2 + h][1] = v.y;
                    av[i * 2 + h][2] = v.z; av[i * 2 + h][3] = v.w;
                }
            #pragma unroll
            for (int j = 0; j < 4; j++)
                #pragma unroll
                for (int e = 0; e < 2; e++) {
                    const int c0 = wn * 32 + j * 8 + dp_b_col + e;
                    const int4 v = *(const int4*)(sb + c0 * SSTR + cb);
                    bv[j * 2 + e][0] = v.x; bv[j * 2 + e][1] = v.y;
                    bv[j * 2 + e][2] = v.z; bv[j * 2 + e][3] = v.w;
                }
            #pragma unroll
            for (int q = 0; q < 4; q++)
                #pragma unroll
                for (int i = 0; i < 4; i++)
                    #pragma unroll
                    for (int h = 0; h < 2; h++)
                        #pragma unroll
                        for (int j = 0; j < 4; j++)
                            #pragma unroll
                            for (int e = 0; e < 2; e++)
                                dp4a_acc(d[i * 4 + j][h * 2 + e],
                                         av[i * 2 + h][q], bv[j * 2 + e][q]);
        }

        if (kt + 2 < NK) load_stage((kt + 2) % GSTAGES, (kt + 2) * BK);
    }

    // epilogue:  out = alpha*D + betx*Sx[i] + betw*Sw[j] + gam + bias[j]
    const float lox = u2f_ord(g_mm[0]), hix = u2f_ord(g_mm[1]);
    const float low = u2f_ord(g_mm[2]), hiw = u2f_ord(g_mm[3]);
    const float sx = (hix - lox) / 255.0f;
    const float sw = (hiw - low) / 255.0f;
    const float tx = 128.0f * sx + lox;
    const float tw = 128.0f * sw + low;
    const float alpha = sx * sw;
    const float betx = sx * tw;
    const float betw = sw * tx;
    const float gam = (float)F_IN * tx * tw;
    const int N = N_ROWS;

    #pragma unroll
    for (int i = 0; i < 4; i++) {
        const int r0 = blockIdx.y * BM + wm * 64 + i * 16 + (lane >> 2);
        const float fx0 = betx * (float)g_sx[r0] + gam;
        const float fx1 = betx * (float)g_sx[r0 + 8] + gam;
        #pragma unroll
        for (int j = 0; j < 4; j++) {
            const int c0 = blockIdx.x * BN + wn * 32 + j * 8 + ((lane & 3) << 1);
            const float e0 = betw * (float)g_sw[c0] + bias[c0];
            const float e1 = betw * (float)g_sw[c0 + 1] + bias[c0 + 1];
            const int* acc = d[i * 4 + j];
            float2 lo2, hi2;
            lo2.x = alpha * (float)acc[0] + fx0 + e0;
            lo2.y = alpha * (float)acc[1] + fx0 + e1;
            hi2.x = alpha * (float)acc[2] + fx1 + e0;
            hi2.y = alpha * (float)acc[3] + fx1 + e1;
            *(float2*)(out + (size_t)r0 * N + c0)       = lo2;
            *(float2*)(out + (size_t)(r0 + 8) * N + c0) = hi2;
        }
    }
}

// ---------------- launch: kernel launches ONLY (graph-capturable) ----------------
extern "C" void kernel_launch(void* const* d_in, const int* in_sizes, int n_in,
                              void* d_out, int out_size)
{
    const float* x    = (const float*)d_in[0];
    const float* w    = (const float*)d_in[1];
    const float* bias = (const float*)d_in[2];
    const float* mats = (const float*)d_in[3];
    const int*   perm = (const int*)d_in[4];
    float* out = (float*)d_out;

    const int rotSmem = 2 * ROT_R * F_IN * (int)sizeof(float);   // 64 KB -> 3 CTAs/SM
    static bool attr_set = false;
    if (!attr_set) {
        cudaFuncSetAttribute(rotate_kernel, cudaFuncAttributeMaxDynamicSharedMemorySize, rotSmem);
        cudaFuncSetAttribute(gemm_kernel, cudaFuncAttributeMaxDynamicSharedMemorySize, GEMM_SMEM);
        attr_set = true;
    }

    init_kernel<<<1, 1>>>();
    prep_kernel<<<(NDR * NBLK + 255) / 256, 256>>>(perm, mats);

    rotate_kernel<<<M_ROWS / ROT_R, ROT_T, rotSmem>>>(x, 0);
    quant_kernel<<<M_ROWS, 256>>>(0);
    rotate_kernel<<<N_ROWS / ROT_R, ROT_T, rotSmem>>>(w, 2);
    quant_kernel<<<N_ROWS, 256>>>(1);

    dim3 grid(N_ROWS / BN, M_ROWS / BM);
    gemm_kernel<<<grid, 256, GEMM_SMEM>>>(bias, out);
}

// round 13
// speedup vs baseline: 1.1972x; 1.1972x over previous
#include <cuda_runtime.h>
#include <cuda_bf16.h>
#include <cstdint>
#include <math.h>

#define F_IN    4096
#define NBLK    2048
#define NROUNDS 12
#define NDR     6          // 6 fused double-rounds
#define M_ROWS  8192
#define N_ROWS  4096

#define ROT_R 4
#define ROT_T 512

// ---------------- scratch (static device arrays; no allocation) ----------------
__device__ float       g_scratch[(size_t)M_ROWS * F_IN];   // 128 MB, reused x then w
__device__ signed char g_qx[(size_t)M_ROWS * F_IN];        // 32 MB
__device__ signed char g_qw[(size_t)N_ROWS * F_IN];        // 16 MB
__device__ int         g_sx[M_ROWS];
__device__ int         g_sw[N_ROWS];
__device__ unsigned    g_mm[4];                            // minx,maxx,minw,maxw (ordered-uint)

// fused double-round tables (prep_kernel output; L2-resident, reused by all CTAs)
__device__ int4   g_fidx[NDR * NBLK];   // 4 source features per dest pair
__device__ float4 g_fw0[NDR * NBLK];    // coeff row for dest element 0
__device__ float4 g_fw1[NDR * NBLK];    // coeff row for dest element 1

__device__ __forceinline__ unsigned f2u_ord(float f) {
    unsigned u = __float_as_uint(f);
    return (u & 0x80000000u) ? ~u : (u | 0x80000000u);
}
__device__ __forceinline__ float u2f_ord(unsigned u) {
    return __uint_as_float((u & 0x80000000u) ? (u ^ 0x80000000u) : ~u);
}

__global__ void init_kernel() {
    g_mm[0] = 0xFFFFFFFFu; g_mm[1] = 0u;
    g_mm[2] = 0xFFFFFFFFu; g_mm[3] = 0u;
}

// ---------------- prep: fuse round pairs (2dr, 2dr+1) into gather4 + 2x4 coeffs ----------------
__global__ __launch_bounds__(256) void prep_kernel(
    const int* __restrict__ perm, const float* __restrict__ mats)
{
    const int idx = blockIdx.x * 256 + threadIdx.x;
    if (idx >= NDR * NBLK) return;
    const int dr = idx / NBLK;
    const int k  = idx % NBLK;
    const int r0 = 2 * dr, r1 = 2 * dr + 1;

    const int j0 = perm[r1 * F_IN + 2 * k];
    const int j1 = perm[r1 * F_IN + 2 * k + 1];
    const int m0 = j0 >> 1, b0 = j0 & 1;
    const int m1 = j1 >> 1, b1 = j1 & 1;

    int4 s;
    s.x = perm[r0 * F_IN + 2 * m0];
    s.y = perm[r0 * F_IN + 2 * m0 + 1];
    s.z = perm[r0 * F_IN + 2 * m1];
    s.w = perm[r0 * F_IN + 2 * m1 + 1];

    const float4* m4 = (const float4*)mats;            // row-major 2x2: {00,01,10,11}
    const float4 M1 = m4[(size_t)r1 * NBLK + k];
    const float4 Ma = m4[(size_t)r0 * NBLK + m0];
    const float4 Mb = m4[(size_t)r0 * NBLK + m1];
    const float a0 = b0 ? Ma.z : Ma.x, a1 = b0 ? Ma.w : Ma.y;   // row bit_b of M_{r0}[m_b]
    const float c0 = b1 ? Mb.z : Mb.x, c1 = b1 ? Mb.w : Mb.y;

    g_fidx[idx] = s;
    g_fw0[idx] = make_float4(M1.x * a0, M1.x * a1, M1.y * c0, M1.y * c1);
    g_fw1[idx] = make_float4(M1.z * a0, M1.z * a1, M1.w * c0, M1.w * c1);
}

// ---------------- rotation: 6 fused stages in smem, feature-interleaved float4 (R11) ----------------
__global__ __launch_bounds__(ROT_T) void rotate_kernel(
    const float* __restrict__ src, int sel)
{
    extern __shared__ float sm[];
    float* bufA = sm;
    float* bufB = sm + ROT_R * F_IN;
    const int tid = threadIdx.x;
    const size_t base = (size_t)blockIdx.x * ROT_R * F_IN;

    // coalesced load of 4 rows (row-major into bufA)
    {
        const float4* g = (const float4*)(src + base);
        float4* b = (float4*)bufA;
        #pragma unroll
        for (int i = 0; i < (ROT_R * F_IN / 4) / ROT_T; i++)
            b[tid + i * ROT_T] = g[tid + i * ROT_T];
    }
    __syncthreads();

    // interleave: bufB4[f] = {row0[f], row1[f], row2[f], row3[f]}
    {
        float4* b4 = (float4*)bufB;
        #pragma unroll
        for (int i = 0; i < F_IN / ROT_T; i++) {
            const int f = tid + i * ROT_T;
            float4 v;
            v.x = bufA[0 * F_IN + f];
            v.y = bufA[1 * F_IN + f];
            v.z = bufA[2 * F_IN + f];
            v.w = bufA[3 * F_IN + f];
            b4[f] = v;
        }
    }
    __syncthreads();

    float* cur = bufB;
    float* nxt = bufA;
    float mn = 3.0e38f, mx = -3.0e38f;

    for (int dr = 0; dr < NDR; dr++) {
        const int4*   fi  = g_fidx + dr * NBLK;
        const float4* w0p = g_fw0 + dr * NBLK;
        const float4* w1p = g_fw1 + dr * NBLK;
        const float4* cur4 = (const float4*)cur;
        float4* nxt4 = (float4*)nxt;
        const bool last = (dr == NDR - 1);
        #pragma unroll
        for (int b = 0; b < NBLK / ROT_T; b++) {
            const int k = tid + b * ROT_T;
            const int4   s  = fi[k];
            const float4 w0 = w0p[k];
            const float4 w1 = w1p[k];
            const float4 va = cur4[s.x];   // LDS.128 gathers
            const float4 vb = cur4[s.y];
            const float4 vc = cur4[s.z];
            const float4 vd = cur4[s.w];
            float4 o0, o1;
            o0.x = w0.x * va.x + w0.y * vb.x + w0.z * vc.x + w0.w * vd.x;
            o0.y = w0.x * va.y + w0.y * vb.y + w0.z * vc.y + w0.w * vd.y;
            o0.z = w0.x * va.z + w0.y * vb.z + w0.z * vc.z + w0.w * vd.z;
            o0.w = w0.x * va.w + w0.y * vb.w + w0.z * vc.w + w0.w * vd.w;
            o1.x = w1.x * va.x + w1.y * vb.x + w1.z * vc.x + w1.w * vd.x;
            o1.y = w1.x * va.y + w1.y * vb.y + w1.z * vc.y + w1.w * vd.y;
            o1.z = w1.x * va.z + w1.y * vb.z + w1.z * vc.z + w1.w * vd.z;
            o1.w = w1.x * va.w + w1.y * vb.w + w1.z * vc.w + w1.w * vd.w;
            nxt4[2 * k]     = o0;
            nxt4[2 * k + 1] = o1;
            if (last) {
                mn = fminf(mn, fminf(fminf(o0.x, o0.y), fminf(o0.z, o0.w)));
                mn = fminf(mn, fminf(fminf(o1.x, o1.y), fminf(o1.z, o1.w)));
                mx = fmaxf(mx, fmaxf(fmaxf(o0.x, o0.y), fmaxf(o0.z, o0.w)));
                mx = fmaxf(mx, fmaxf(fmaxf(o1.x, o1.y), fmaxf(o1.z, o1.w)));
            }
        }
        __syncthreads();
        float* t = cur; cur = nxt; nxt = t;
    }

    // un-interleave in registers, write row-major scratch (coalesced per row)
    {
        const float4* cur4 = (const float4*)cur;
        float* dst = g_scratch + base;
        #pragma unroll
        for (int i = 0; i < F_IN / ROT_T; i++) {
            const int f = tid + i * ROT_T;
            const float4 v = cur4[f];
            dst[0 * F_IN + f] = v.x;
            dst[1 * F_IN + f] = v.y;
            dst[2 * F_IN + f] = v.z;
            dst[3 * F_IN + f] = v.w;
        }
    }

    // block-reduce min/max -> one atomic pair per CTA
    #pragma unroll
    for (int o = 16; o > 0; o >>= 1) {
        mn = fminf(mn, __shfl_xor_sync(0xFFFFFFFFu, mn, o));
        mx = fmaxf(mx, __shfl_xor_sync(0xFFFFFFFFu, mx, o));
    }
    __shared__ float smn[ROT_T / 32], smx[ROT_T / 32];
    const int w = tid >> 5;
    if ((tid & 31) == 0) { smn[w] = mn; smx[w] = mx; }
    __syncthreads();
    if (tid == 0) {
        #pragma unroll
        for (int i = 1; i < ROT_T / 32; i++) {
            mn = fminf(mn, smn[i]); mx = fmaxf(mx, smx[i]);
        }
        atomicMin(&g_mm[sel], f2u_ord(mn));
        atomicMax(&g_mm[sel + 1], f2u_ord(mx));
    }
}

// ---------------- quantize: q = clip(round((t-lo)/s) - 128), + per-row sums ----------------
__global__ __launch_bounds__(256) void quant_kernel(int sel)
{
    const int row = blockIdx.x;
    const int tid = threadIdx.x;
    signed char* q = sel ? g_qw : g_qx;
    int* rowsum    = sel ? g_sw : g_sx;
    const float lo = u2f_ord(g_mm[sel ? 2 : 0]);
    const float hi = u2f_ord(g_mm[sel ? 3 : 1]);
    const float scale = (hi - lo) / 255.0f;

    const float4* s4 = (const float4*)(g_scratch + (size_t)row * F_IN);
    char4* q4 = (char4*)(q + (size_t)row * F_IN);
    int ssum = 0;
    #pragma unroll
    for (int i = 0; i < (F_IN / 4) / 256; i++) {
        const float4 v = s4[tid + i * 256];
        const int q0 = (int)fminf(fmaxf(rintf((v.x - lo) / scale) - 128.0f, -128.0f), 127.0f);
        const int q1 = (int)fminf(fmaxf(rintf((v.y - lo) / scale) - 128.0f, -128.0f), 127.0f);
        const int q2 = (int)fminf(fmaxf(rintf((v.z - lo) / scale) - 128.0f, -128.0f), 127.0f);
        const int q3 = (int)fminf(fmaxf(rintf((v.w - lo) / scale) - 128.0f, -128.0f), 127.0f);
        ssum += q0 + q1 + q2 + q3;
        char4 c;
        c.x = (signed char)q0; c.y = (signed char)q1;
        c.z = (signed char)q2; c.w = (signed char)q3;
        q4[tid + i * 256] = c;
    }
    #pragma unroll
    for (int o = 16; o > 0; o >>= 1)
        ssum += __shfl_xor_sync(0xFFFFFFFFu, ssum, o);
    __shared__ int ss[8];
    if ((tid & 31) == 0) ss[tid >> 5] = ssum;
    __syncthreads();
    if (tid == 0) {
        #pragma unroll
        for (int i = 1; i < 8; i++) ssum += ss[i];
        rowsum[row] = ssum;
    }
}

// ---------------- hybrid int8 GEMM: IMMA + dp4a INTERLEAVED per ks-step ----------------
// Per BK=128 tile: K[0:96] via 3 IMMA ks-steps; K[96:128] via dp4a chunks issued
// immediately after ks=0 and ks=1 mma blocks, so ALU-pipe work fills mma-accept
// backpressure stalls. dp4a mapping matches the mma d-fragment layout exactly
// (correctness proven in R12: identical rel_err).
#define BM 128
#define BN 128
#define BK 128
#define GSTAGES 3
#define SSTR 144

#define A_STAGE_BYTES (BM * SSTR)
#define B_STAGE_BYTES (BN * SSTR)
#define GEMM_SMEM (GSTAGES * (A_STAGE_BYTES + B_STAGE_BYTES))

__device__ __forceinline__ void cp16(void* s, const void* g) {
    unsigned sa = (unsigned)__cvta_generic_to_shared(s);
    asm volatile("cp.async.cg.shared.global [%0], [%1], 16;\n" :: "r"(sa), "l"(g));
}
__device__ __forceinline__ void cp_commit() { asm volatile("cp.async.commit_group;\n"); }
__device__ __forceinline__ void cp_wait1()  { asm volatile("cp.async.wait_group 1;\n"); }
__device__ __forceinline__ void cp_wait0()  { asm volatile("cp.async.wait_group 0;\n"); }

__device__ __forceinline__ void ldsm4(int* r, const void* p) {
    unsigned a = (unsigned)__cvta_generic_to_shared(p);
    asm volatile("ldmatrix.sync.aligned.m8n8.x4.shared.b16 {%0,%1,%2,%3}, [%4];\n"
                 : "=r"(r[0]), "=r"(r[1]), "=r"(r[2]), "=r"(r[3]) : "r"(a));
}
__device__ __forceinline__ void ldsm2(int* r, const void* p) {
    unsigned a = (unsigned)__cvta_generic_to_shared(p);
    asm volatile("ldmatrix.sync.aligned.m8n8.x2.shared.b16 {%0,%1}, [%2];\n"
                 : "=r"(r[0]), "=r"(r[1]) : "r"(a));
}

__device__ __forceinline__ void mma_s8(int* d, const int* a, const int* b) {
    asm volatile(
        "mma.sync.aligned.m16n8k32.row.col.s32.s8.s8.s32 "
        "{%0,%1,%2,%3}, {%4,%5,%6,%7}, {%8,%9}, {%0,%1,%2,%3};\n"
        : "+r"(d[0]), "+r"(d[1]), "+r"(d[2]), "+r"(d[3])
        : "r"(a[0]), "r"(a[1]), "r"(a[2]), "r"(a[3]), "r"(b[0]), "r"(b[1]));
}

__device__ __forceinline__ void dp4a_acc(int& d, int a, int b) {
    asm volatile("dp4a.s32.s32 %0, %1, %2, %0;\n" : "+r"(d) : "r"(a), "r"(b));
}

__global__ __launch_bounds__(256, 1) void gemm_kernel(
    const float* __restrict__ bias, float* __restrict__ out)
{
    extern __shared__ signed char gsm[];
    const signed char* __restrict__ A = g_qx;   // [M][K]
    const signed char* __restrict__ B = g_qw;   // [N][K]
    const int K = F_IN;
    const int tid = threadIdx.x;
    const int lane = tid & 31;
    const int warp = tid >> 5;
    const int wm = warp & 1;    // 2 warps along M (64 rows each)
    const int wn = warp >> 1;   // 4 warps along N (32 cols each)
    const size_t aBase = (size_t)blockIdx.y * BM * K;
    const size_t bBase = (size_t)blockIdx.x * BN * K;

    int d[16][4];
    #pragma unroll
    for (int i = 0; i < 16; i++) { d[i][0] = d[i][1] = d[i][2] = d[i][3] = 0; }

    auto load_stage = [&](int st, int k0) {
        signed char* sa = gsm + st * A_STAGE_BYTES;
        signed char* sb = gsm + GSTAGES * A_STAGE_BYTES + st * B_STAGE_BYTES;
        #pragma unroll
        for (int i = 0; i < 4; i++) {
            const int idx = tid + i * 256;          // 1024 x 16B per matrix
            const int row = idx >> 3;
            const int c = (idx & 7) << 4;
            cp16(sa + row * SSTR + c, A + aBase + (size_t)row * K + k0 + c);
            cp16(sb + row * SSTR + c, B + bBase + (size_t)row * K + k0 + c);
        }
        cp_commit();
    };

    load_stage(0, 0);
    load_stage(1, BK);

    const int a_row_off = ((lane >> 3) & 1) * 8 + (lane & 7);
    const int a_col_off = (lane >> 4) * 16;
    const int b_row_off = (lane & 7);
    const int b_col_off = ((lane >> 3) & 1) * 16;
    const int dp_a_row = lane >> 2;          // dp4a A row within 8-group
    const int dp_b_col = (lane & 3) << 1;    // dp4a B col pair base

    const int NK = K / BK;   // 32
    for (int kt = 0; kt < NK; kt++) {
        const int st = kt % GSTAGES;
        if (kt + 2 < NK) cp_wait1(); else cp_wait0();
        __syncthreads();

        const signed char* sa = gsm + st * A_STAGE_BYTES;
        const signed char* sb = gsm + GSTAGES * A_STAGE_BYTES + st * B_STAGE_BYTES;

        #pragma unroll
        for (int ks = 0; ks < 3; ks++) {
            // --- tensor pipe: one IMMA ks-step over K[32ks : 32ks+32] ---
            const int cb = ks * 32;
            int a[4][4], b[4][2];
            #pragma unroll
            for (int i = 0; i < 4; i++) {
                const int r0 = wm * 64 + i * 16 + a_row_off;
                ldsm4(a[i], sa + r0 * SSTR + cb + a_col_off);
            }
            #pragma unroll
            for (int j = 0; j < 4; j++) {
                const int n0 = wn * 32 + j * 8 + b_row_off;
                ldsm2(b[j], sb + n0 * SSTR + cb + b_col_off);
            }
            #pragma unroll
            for (int i = 0; i < 4; i++)
                #pragma unroll
                for (int j = 0; j < 4; j++)
                    mma_s8(d[i * 4 + j], a[i], b[j]);

            // --- ALU pipe: dp4a chunk over K[96+16ks : 112+16ks], ks=0,1 ---
            // Issued right after the mma block so it fills mma-accept stalls.
            if (ks < 2) {
                const int cb2 = 96 + ks * 16;
                int bv[8][4];
                #pragma unroll
                for (int j = 0; j < 4; j++)
                    #pragma unroll
                    for (int e = 0; e < 2; e++) {
                        const int c0 = wn * 32 + j * 8 + dp_b_col + e;
                        const int4 v = *(const int4*)(sb + c0 * SSTR + cb2);
                        bv[j * 2 + e][0] = v.x; bv[j * 2 + e][1] = v.y;
                        bv[j * 2 + e][2] = v.z; bv[j * 2 + e][3] = v.w;
                    }
                #pragma unroll
                for (int i = 0; i < 4; i++) {
                    int av0[4], av1[4];
                    {
                        const int r0 = wm * 64 + i * 16 + dp_a_row;
                        const int4 v0 = *(const int4*)(sa + r0 * SSTR + cb2);
                        const int4 v1 = *(const int4*)(sa + (r0 + 8) * SSTR + cb2);
                        av0[0] = v0.x; av0[1] = v0.y; av0[2] = v0.z; av0[3] = v0.w;
                        av1[0] = v1.x; av1[1] = v1.y; av1[2] = v1.z; av1[3] = v1.w;
                    }
                    #pragma unroll
                    for (int q = 0; q < 4; q++)
                        #pragma unroll
                        for (int j = 0; j < 4; j++)
                            #pragma unroll
                            for (int e = 0; e < 2; e++) {
                                dp4a_acc(d[i * 4 + j][e],     av0[q], bv[j * 2 + e][q]);
                                dp4a_acc(d[i * 4 + j][2 + e], av1[q], bv[j * 2 + e][q]);
                            }
                }
            }
        }

        if (kt + 2 < NK) load_stage((kt + 2) % GSTAGES, (kt + 2) * BK);
    }

    // epilogue:  out = alpha*D + betx*Sx[i] + betw*Sw[j] + gam + bias[j]
    const float lox = u2f_ord(g_mm[0]), hix = u2f_ord(g_mm[1]);
    const float low = u2f_ord(g_mm[2]), hiw = u2f_ord(g_mm[3]);
    const float sx = (hix - lox) / 255.0f;
    const float sw = (hiw - low) / 255.0f;
    const float tx = 128.0f * sx + lox;
    const float tw = 128.0f * sw + low;
    const float alpha = sx * sw;
    const float betx = sx * tw;
    const float betw = sw * tx;
    const float gam = (float)F_IN * tx * tw;
    const int N = N_ROWS;

    #pragma unroll
    for (int i = 0; i < 4; i++) {
        const int r0 = blockIdx.y * BM + wm * 64 + i * 16 + (lane >> 2);
        const float fx0 = betx * (float)g_sx[r0] + gam;
        const float fx1 = betx * (float)g_sx[r0 + 8] + gam;
        #pragma unroll
        for (int j = 0; j < 4; j++) {
            const int c0 = blockIdx.x * BN + wn * 32 + j * 8 + ((lane & 3) << 1);
            const float e0 = betw * (float)g_sw[c0] + bias[c0];
            const float e1 = betw * (float)g_sw[c0 + 1] + bias[c0 + 1];
            const int* acc = d[i * 4 + j];
            float2 lo2, hi2;
            lo2.x = alpha * (float)acc[0] + fx0 + e0;
            lo2.y = alpha * (float)acc[1] + fx0 + e1;
            hi2.x = alpha * (float)acc[2] + fx1 + e0;
            hi2.y = alpha * (float)acc[3] + fx1 + e1;
            *(float2*)(out + (size_t)r0 * N + c0)       = lo2;
            *(float2*)(out + (size_t)(r0 + 8) * N + c0) = hi2;
        }
    }
}

// ---------------- launch: kernel launches ONLY (graph-capturable) ----------------
extern "C" void kernel_launch(void* const* d_in, const int* in_sizes, int n_in,
                              void* d_out, int out_size)
{
    const float* x    = (const float*)d_in[0];
    const float* w    = (const float*)d_in[1];
    const float* bias = (const float*)d_in[2];
    const float* mats = (const float*)d_in[3];
    const int*   perm = (const int*)d_in[4];
    float* out = (float*)d_out;

    const int rotSmem = 2 * ROT_R * F_IN * (int)sizeof(float);   // 128 KB
    static bool attr_set = false;
    if (!attr_set) {
        cudaFuncSetAttribute(rotate_kernel, cudaFuncAttributeMaxDynamicSharedMemorySize, rotSmem);
        cudaFuncSetAttribute(gemm_kernel, cudaFuncAttributeMaxDynamicSharedMemorySize, GEMM_SMEM);
        attr_set = true;
    }

    init_kernel<<<1, 1>>>();
    prep_kernel<<<(NDR * NBLK + 255) / 256, 256>>>(perm, mats);

    rotate_kernel<<<M_ROWS / ROT_R, ROT_T, rotSmem>>>(x, 0);
    quant_kernel<<<M_ROWS, 256>>>(0);
    rotate_kernel<<<N_ROWS / ROT_R, ROT_T, rotSmem>>>(w, 2);
    quant_kernel<<<N_ROWS, 256>>>(1);

    dim3 grid(N_ROWS / BN, M_ROWS / BM);
    gemm_kernel<<<grid, 256, GEMM_SMEM>>>(bias, out);
}